// round 16
// baseline (speedup 1.0000x reference)
#include <cuda_runtime.h>
#include <cuda_bf16.h>
#include <cstdint>

// Problem constants
#define M_ROWS  200000      // BATCH * SIM_T
#define K_DIM   784
#define N1      100
#define T_STEPS 2000
#define BATCH   100
#define N2      10
// phase split: t in [0,1200) and [1200,2000)
#define T_SPLIT 1200
#define ROWS0   120000
#define ROWS1   80000
#define HCH0    938         // ceil(120000/128)
#define HCH1    625         // 80000/128
#define NSCAN   50          // scan blocks (2 batches each)

// Scratch.
// g_z1 layout: [t][batch][c]  (row r' = t*100 + b). Padded to t=2008.
__device__ float  g_z1[(size_t)2008 * BATCH * N1];           // 80 MB
__device__ float  g_T1[(size_t)M_ROWS * N1];                 // 80 MB  [b][t][c]
__device__ float  g_z2t[(size_t)BATCH * N2 * T_STEPS + 16];  // 8 MB  [b*10+o][t]
__device__ int    g_flagA[944];                              // phase-1 chunk flags
__device__ int    g_flagB[640];                              // phase-2 chunk flags
__device__ float4 g_S1[BATCH * N1];                          // L1 state @ t=1200
__device__ float4 g_S2[BATCH * N2];                          // L2 state @ t=1200
__device__ __align__(16) __nv_bfloat16 g_W1h[112 * K_DIM];
__device__ __align__(16) __nv_bfloat16 g_W1l[112 * K_DIM];

// ---------------------------------------------------------------------------
// helpers
// ---------------------------------------------------------------------------
__device__ __forceinline__ unsigned pack_bf16x2(float fhi, float flo) {
    unsigned r;
    asm("cvt.rn.bf16x2.f32 %0, %1, %2;" : "=r"(r) : "f"(fhi), "f"(flo));
    return r;
}
__device__ __forceinline__ void mma_bf16(float* c, const unsigned* a,
                                         unsigned b0, unsigned b1) {
    asm("mma.sync.aligned.m16n8k16.row.col.f32.bf16.bf16.f32 "
        "{%0,%1,%2,%3}, {%4,%5,%6,%7}, {%8,%9}, {%0,%1,%2,%3};"
        : "+f"(c[0]), "+f"(c[1]), "+f"(c[2]), "+f"(c[3])
        : "r"(a[0]), "r"(a[1]), "r"(a[2]), "r"(a[3]), "r"(b0), "r"(b1));
}

// ---------------------------------------------------------------------------
// K0: convert W1 -> bf16 hi/lo (112 rows) + reset flags
// ---------------------------------------------------------------------------
__global__ void w1_convert_kernel(const float* __restrict__ W1) {
    int idx = blockIdx.x * 256 + threadIdx.x;
    if (idx < 944) g_flagA[idx] = 0;
    if (idx < 640) g_flagB[idx] = 0;
    if (idx >= 112 * K_DIM) return;
    int r = idx / K_DIM;
    float w = (r < N1) ? W1[idx] : 0.f;
    __nv_bfloat16 hb = __float2bfloat16_rn(w);
    float hf = __bfloat162float(hb);
    g_W1h[idx] = hb;
    g_W1l[idx] = __float2bfloat16_rn(w - hf);
}

// ---------------------------------------------------------------------------
// HH step math (exact round-9 version)
// ---------------------------------------------------------------------------
__device__ __forceinline__ float ex2a(float x) {
    float r; asm("ex2.approx.f32 %0, %1;" : "=f"(r) : "f"(x)); return r;
}
__device__ __forceinline__ float rcpa(float x) {
    float r; asm("rcp.approx.f32 %0, %1;" : "=f"(r) : "f"(x)); return r;
}

#define L9   0.1602994489863f
#define L12  0.1202245867397f
#define L3   0.4808983469589f
#define BH_C 0.0023508962f
#define S0V  9.357622969e-14f

__device__ __forceinline__ float hh_step_t(float zk, float& V, float& m, float& n, float& h) {
    float mm   = m * m;
    float pow1 = 40.f * (mm * m) * h;
    float nn   = n * n;
    float pow2 = 35.f * (nn * nn);
    float Gs = 0.005f * (pow1 + pow2 + 0.3f);
    float E  = fmaf(pow1, 55.f, fmaf(pow2, -77.f, -19.5f));
    float num = fmaf(V, (1.f - Gs), 0.01f * (E + 1.5f + zk));
    float Vn = num * rcpa(1.f + Gs);

    float dM = Vn + 35.f;
    float dN = Vn - 25.f;
    float uM = ex2a(dM * L9);
    float uN = ex2a(dN * L9);
    float w  = ex2a((Vn + 90.f) * L12);
    float eS = ex2a((20.f - Vn) * L3);

    float um1M = uM - 1.f;
    float sM = 0.005f * dM * fmaf(0.182f, uM, 0.124f);
    float um1N = uN - 1.f;
    float sN = 0.005f * dN * fmaf(0.02f, uN, 0.002f);
    float sH = fmaf(0.005f * BH_C, w * w, 0.00125f);

    float rM = rcpa(um1M + sM);
    float rN = rcpa(um1N + sN);
    float rH = rcpa(w + sH);
    float rS = rcpa(1.f + eS);

    float mN = fmaf(0.00182f * dM, uM, (um1M - sM) * m) * rM;
    float nN = fmaf(0.0002f * dN, uN, (um1N - sN) * n) * rN;
    float hN = fmaf(w - sH, h, 0.0025f) * rH;

    if (Vn == 25.f)  nN = fmaf(0.99901f, n, 0.0018f) * (1.f / 1.00099f);
    if (Vn == -35.f) mN = fmaf(0.98623f, m, 0.01638f) * (1.f / 1.01377f);

    m = mN; n = nN; h = hN;
    V = Vn;
    return rS;
}

// ---------------------------------------------------------------------------
// wait until chunk flags [clo, chi] are all set (warp-parallel volatile poll)
// ---------------------------------------------------------------------------
__device__ __forceinline__ void wait_chunks(const int* flags, int clo, int chi) {
    const int lane = threadIdx.x & 31;
    for (int base = clo; base <= chi; base += 32) {
        int cid = min(base + lane, chi);
        while (__any_sync(0xffffffffu, ((volatile const int*)flags)[cid] == 0))
            __nanosleep(64);
    }
    __threadfence();
}

// ---------------------------------------------------------------------------
// K1/K3: fused GEMM-phase + L1-phase (+ L2-part1 blocks in phase 1).
//   blocks [0,50): L1 producers, TWO batches each (warps 0-3: batch 2k,
//                  warps 4-7: batch 2k+1; fully independent flag-waits).
//   phase 1 only, blocks [50,58): L2 steps 0..1199 (inputs ready at launch).
//   remaining blocks: GEMM chunk for this phase, publishes flag.
// ---------------------------------------------------------------------------
#define NSTAGE 49

__global__ void __launch_bounds__(256, 2)
fused_half(const float* __restrict__ A, float* __restrict__ out, int phase) {
    __shared__ unsigned Ahs[2][128 * 8];
    __shared__ unsigned Als[2][128 * 8];
    __shared__ unsigned Bhs[2][112 * 8];
    __shared__ unsigned Bls[2][112 * 8];

    const int blk = blockIdx.x;
    const int tid = threadIdx.x;
    const int gemmBase = NSCAN + (phase ? 8 : 0);
    int* flags = phase ? g_flagB : g_flagA;

    if (blk < NSCAN) {
        // ============ L1 producers, batches 2*blk and 2*blk+1 ============
        const int sub = tid >> 7;          // 0 or 1
        const int t2  = tid & 127;
        const int b   = blk * 2 + sub;
        const bool act = (t2 < N1);
        const int s0   = phase ? T_SPLIT : 0;
        const int tcap = phase ? 1999 : (T_SPLIT - 1);
        const int w0   = phase ? 24 : 0;
        const int nw   = phase ? 16 : 24;
        const int roff = phase ? ROWS0 : 0;
        const int maxc = phase ? (HCH1 - 1) : (HCH0 - 1);

        float V = -70.f, m = 0.f, n = 0.f, h = 1.f;
        float p0 = 0.f, p1 = 0.f, p2 = 0.f, p3 = 0.f;

        const float* zq = g_z1 + (size_t)b * N1 + t2 + (size_t)s0 * 10000;
        const float* zl = zq + 4 * 10000;
        float* ts = g_T1 + (size_t)b * T_STEPS * N1 + t2 + (size_t)(s0 + 1) * N1;

        wait_chunks(flags, 0, 3);          // z1 t-rows s0..s0+3
        if (act) {
            if (phase == 0) {
                g_T1[(size_t)b * T_STEPS * N1 + t2] = S0V;   // T1 row 0
            } else {
                float4 st = g_S1[b * N1 + t2];
                V = st.x; m = st.y; n = st.z; h = st.w;
            }
            p0 = zq[0];
            p1 = zq[10000];
            p2 = zq[20000];
            p3 = zq[30000];
        }

#pragma unroll 1
        for (int w = 0; w < nw; w++) {
            const int wg = w0 + w;
            int tlo = wg * 50 + 4;
            int thi = min(wg * 50 + 53, tcap);
            int rlo = tlo * 100 - roff;
            int rhi = thi * 100 + 99 - roff;
            wait_chunks(flags, rlo >> 7, min(rhi >> 7, maxc));
            const int steps = (wg == 39) ? 49 : 50;
            if (act) {
#pragma unroll 2
                for (int j = 0; j < steps; j++) {
                    float zc = p0;
                    p0 = p1; p1 = p2; p2 = p3; p3 = *zl; zl += 10000;
                    *ts = hh_step_t(zc, V, m, n, h);
                    ts += N1;
                }
            }
        }
        if (act && phase == 0)
            g_S1[b * N1 + t2] = make_float4(V, m, n, h);
        return;
    }

    if (blk < gemmBase) {
        // ============ L2 part-1: steps 0..1199 (phase 1 only) ============
        if (tid >= 128) return;
        const int idx = (blk - NSCAN) * 128 + tid;
        if (idx >= BATCH * N2) return;
        const int b = idx / N2;
        const int o = idx - b * N2;

        const float* zl = g_z2t + (size_t)idx * T_STEPS;
        float* os = out + (size_t)b * T_STEPS * N2 + o;

        float V = -70.f, m = 0.f, n = 0.f, h = 1.f;
        os[0] = S0V;
        os += N2;

        float p0 = zl[0], p1 = zl[1], p2 = zl[2], p3 = zl[3];
        zl += 4;

#pragma unroll 1
        for (int s4 = 0; s4 < T_SPLIT; s4 += 4) {
#pragma unroll
            for (int j = 0; j < 4; j++) {
                float zc = p0;
                p0 = p1; p1 = p2; p2 = p3; p3 = *zl; zl++;
                *os = hh_step_t(zc, V, m, n, h);
                os += N2;
            }
        }
        g_S2[idx] = make_float4(V, m, n, h);
        return;
    }

    // ================= GEMM chunk (this phase) =================
    const int chunk = blk - gemmBase;
    const int roff  = phase ? ROWS0 : 0;
    const int row0  = roff + chunk * 128;
    const int limit = roff + (phase ? ROWS1 : ROWS0);

    const int warp = tid >> 5, lane = tid & 31;
    const int g    = lane >> 2, tig = lane & 3;
    const int wm   = (warp >> 1) * 32;
    const int wn   = (warp & 1) * 56;

    // per-thread A row pointers (r' = t*100+b -> A row b*2000+t)
    const float* aptr[2];
    bool av[2];
    {
#pragma unroll
        for (int i = 0; i < 2; i++) {
            int idx = tid + i * 256;
            int rp = row0 + (idx >> 2);
            av[i] = rp < limit;
            int rc = av[i] ? rp : 0;
            int t = rc / 100;
            int bb = rc - t * 100;
            aptr[i] = A + (size_t)(bb * 2000 + t) * K_DIM + (idx & 3) * 4;
        }
    }

    float acc[2][7][4];
#pragma unroll
    for (int i = 0; i < 2; i++)
#pragma unroll
        for (int j = 0; j < 7; j++)
#pragma unroll
            for (int q = 0; q < 4; q++) acc[i][j][q] = 0.f;

    float4 va[2];
    unsigned vbh[4], vbl[4];

    auto ldg_stage = [&](int s) {
        int k0 = s * 16;
#pragma unroll
        for (int i = 0; i < 2; i++)
            va[i] = av[i] ? *(const float4*)(aptr[i] + k0)
                          : make_float4(0.f, 0.f, 0.f, 0.f);
#pragma unroll
        for (int i = 0; i < 4; i++) {
            int idx = tid + i * 256;
            if (idx < 896) {
                int r = idx >> 3, j = idx & 7;
                size_t off = (size_t)r * (K_DIM / 2) + (k0 >> 1) + j;
                vbh[i] = ((const unsigned*)g_W1h)[off];
                vbl[i] = ((const unsigned*)g_W1l)[off];
            }
        }
    };
    auto sts_stage = [&](int buf) {
#pragma unroll
        for (int i = 0; i < 2; i++) {
            int idx = tid + i * 256;
            int r = idx >> 2, q = idx & 3;
            float4 v = va[i];
            unsigned h0 = pack_bf16x2(v.y, v.x);
            unsigned h1 = pack_bf16x2(v.w, v.z);
            float f0h = __uint_as_float(h0 << 16);
            float f1h = __uint_as_float(h0 & 0xffff0000u);
            float f2h = __uint_as_float(h1 << 16);
            float f3h = __uint_as_float(h1 & 0xffff0000u);
            unsigned l0 = pack_bf16x2(v.y - f1h, v.x - f0h);
            unsigned l1 = pack_bf16x2(v.w - f3h, v.z - f2h);
            int sw = r & 7;
            Ahs[buf][r * 8 + ((2 * q)     ^ sw)] = h0;
            Ahs[buf][r * 8 + ((2 * q + 1) ^ sw)] = h1;
            Als[buf][r * 8 + ((2 * q)     ^ sw)] = l0;
            Als[buf][r * 8 + ((2 * q + 1) ^ sw)] = l1;
        }
#pragma unroll
        for (int i = 0; i < 4; i++) {
            int idx = tid + i * 256;
            if (idx < 896) {
                int r = idx >> 3, j = idx & 7;
                Bhs[buf][r * 8 + (j ^ (r & 7))] = vbh[i];
                Bls[buf][r * 8 + (j ^ (r & 7))] = vbl[i];
            }
        }
    };

    ldg_stage(0);
    sts_stage(0);
    __syncthreads();

#pragma unroll 1
    for (int s = 0; s < NSTAGE; s++) {
        if (s + 1 < NSTAGE) ldg_stage(s + 1);

        const int buf = s & 1;
        unsigned a_h[2][4], a_l[2][4];
#pragma unroll
        for (int mt = 0; mt < 2; mt++) {
            int r0 = wm + mt * 16 + g, r1 = r0 + 8;
            int s0 = r0 & 7, s1 = r1 & 7;
            a_h[mt][0] = Ahs[buf][r0 * 8 + (tig ^ s0)];
            a_h[mt][1] = Ahs[buf][r1 * 8 + (tig ^ s1)];
            a_h[mt][2] = Ahs[buf][r0 * 8 + ((tig + 4) ^ s0)];
            a_h[mt][3] = Ahs[buf][r1 * 8 + ((tig + 4) ^ s1)];
            a_l[mt][0] = Als[buf][r0 * 8 + (tig ^ s0)];
            a_l[mt][1] = Als[buf][r1 * 8 + (tig ^ s1)];
            a_l[mt][2] = Als[buf][r0 * 8 + ((tig + 4) ^ s0)];
            a_l[mt][3] = Als[buf][r1 * 8 + ((tig + 4) ^ s1)];
        }
#pragma unroll
        for (int nt = 0; nt < 7; nt++) {
            int n = wn + nt * 8 + g;
            int sn = n & 7;
            unsigned b0h = Bhs[buf][n * 8 + (tig ^ sn)];
            unsigned b1h = Bhs[buf][n * 8 + ((tig + 4) ^ sn)];
            unsigned b0l = Bls[buf][n * 8 + (tig ^ sn)];
            unsigned b1l = Bls[buf][n * 8 + ((tig + 4) ^ sn)];
#pragma unroll
            for (int mt = 0; mt < 2; mt++) {
                mma_bf16(acc[mt][nt], a_h[mt], b0h, b1h);
                mma_bf16(acc[mt][nt], a_h[mt], b0l, b1l);
                mma_bf16(acc[mt][nt], a_l[mt], b0h, b1h);
            }
        }

        if (s + 1 < NSTAGE) sts_stage((s + 1) & 1);
        __syncthreads();
    }

#pragma unroll
    for (int mt = 0; mt < 2; mt++) {
#pragma unroll
        for (int nt = 0; nt < 7; nt++) {
            int c = wn + nt * 8 + 2 * tig;
            if (c >= 99) continue;
            int r0g = row0 + wm + mt * 16 + g;
            if (r0g < limit) {
                float2 v = make_float2(acc[mt][nt][0], acc[mt][nt][1]);
                *(float2*)(g_z1 + (size_t)r0g * N1 + c) = v;
            }
            if (r0g + 8 < limit) {
                float2 v = make_float2(acc[mt][nt][2], acc[mt][nt][3]);
                *(float2*)(g_z1 + (size_t)(r0g + 8) * N1 + c) = v;
            }
        }
    }

    // publish chunk
    __threadfence();
    __syncthreads();
    if (tid == 0) atomicExch(&flags[chunk], 1);
}

// ---------------------------------------------------------------------------
// K2/K4: z2t[b*10+o][t] = sum_k T1[b][t][k] * W2[o][k]  for t in [toff, toff+cnt)
// ---------------------------------------------------------------------------
__global__ void __launch_bounds__(256, 4)
z2_part(const float* __restrict__ W2, int toff, int cnt) {
    __shared__ float W2s[N1][12];

    const int tid = threadIdx.x;
    for (int i = tid; i < N1 * 12; i += 256) {
        int k = i / 12, o = i - k * 12;
        W2s[k][o] = (o < N2) ? W2[o * N1 + k] : 0.f;
    }
    __syncthreads();

    const int u = blockIdx.x * 256 + tid;
    if (u >= BATCH * cnt) return;
    const int b = u / cnt;
    const int t = (u - b * cnt) + toff;

    const float4* tr = (const float4*)(g_T1 + ((size_t)b * T_STEPS + t) * N1);
    float acc[12];
#pragma unroll
    for (int o = 0; o < 12; o++) acc[o] = 0.f;

#pragma unroll 5
    for (int k4 = 0; k4 < 25; k4++) {
        float4 tv = tr[k4];
        const float* tf = &tv.x;
#pragma unroll
        for (int kk = 0; kk < 4; kk++) {
            int k = k4 * 4 + kk;
            float4 w0 = *(const float4*)&W2s[k][0];
            float4 w1 = *(const float4*)&W2s[k][4];
            float4 w2 = *(const float4*)&W2s[k][8];
            float f = tf[kk];
            acc[0] = fmaf(f, w0.x, acc[0]);  acc[1] = fmaf(f, w0.y, acc[1]);
            acc[2] = fmaf(f, w0.z, acc[2]);  acc[3] = fmaf(f, w0.w, acc[3]);
            acc[4] = fmaf(f, w1.x, acc[4]);  acc[5] = fmaf(f, w1.y, acc[5]);
            acc[6] = fmaf(f, w1.z, acc[6]);  acc[7] = fmaf(f, w1.w, acc[7]);
            acc[8] = fmaf(f, w2.x, acc[8]);  acc[9] = fmaf(f, w2.y, acc[9]);
        }
    }
#pragma unroll
    for (int o = 0; o < N2; o++)
        g_z2t[((size_t)b * N2 + o) * T_STEPS + t] = acc[o];
}

// ---------------------------------------------------------------------------
// K5: layer-2 tail (steps 1200..1998), state reloaded
// ---------------------------------------------------------------------------
__global__ void __launch_bounds__(128, 1)
l2_tail(float* __restrict__ out) {
    const int idx = blockIdx.x * 128 + threadIdx.x;
    if (idx >= BATCH * N2) return;
    const int b = idx / N2;
    const int o = idx - b * N2;

    const float* zl = g_z2t + (size_t)idx * T_STEPS + T_SPLIT;
    float* os = out + ((size_t)b * T_STEPS + T_SPLIT + 1) * N2 + o;

    float4 st = g_S2[idx];
    float V = st.x, m = st.y, n = st.z, h = st.w;

    float p0 = zl[0], p1 = zl[1], p2 = zl[2], p3 = zl[3];
    zl += 4;

    // 799 steps = 199*4 + 3
#pragma unroll 1
    for (int s4 = 0; s4 < 796; s4 += 4) {
#pragma unroll
        for (int j = 0; j < 4; j++) {
            float zc = p0;
            p0 = p1; p1 = p2; p2 = p3; p3 = *zl; zl++;
            *os = hh_step_t(zc, V, m, n, h);
            os += N2;
        }
    }
#pragma unroll
    for (int j = 0; j < 3; j++) {
        float zc = p0;
        p0 = p1; p1 = p2; p2 = p3; p3 = *zl; zl++;
        *os = hh_step_t(zc, V, m, n, h);
        os += N2;
    }
}

// ---------------------------------------------------------------------------
extern "C" void kernel_launch(void* const* d_in, const int* in_sizes, int n_in,
                              void* d_out, int out_size) {
    const float* batch = (const float*)d_in[0];   // (100, 2000, 784)
    const float* W1    = (const float*)d_in[1];   // (100, 784)
    const float* W2    = (const float*)d_in[2];   // (10, 100)
    float* out = (float*)d_out;                   // (100, 2000, 10)

    w1_convert_kernel<<<(112 * K_DIM + 255) / 256, 256>>>(W1);
    fused_half<<<NSCAN + HCH0, 256>>>(batch, out, 0);        // GEMM p1 + L1 p1
    z2_part<<<(BATCH * T_SPLIT + 255) / 256, 256>>>(W2, 0, T_SPLIT);
    fused_half<<<NSCAN + 8 + HCH1, 256>>>(batch, out, 1);    // GEMM p2 + L1 p2 + L2 p1
    z2_part<<<(BATCH * (T_STEPS - T_SPLIT) + 255) / 256, 256>>>(W2, T_SPLIT, T_STEPS - T_SPLIT);
    l2_tail<<<8, 128>>>(out);                                // L2 p2
}

// round 17
// speedup vs baseline: 1.1714x; 1.1714x over previous
#include <cuda_runtime.h>
#include <cuda_bf16.h>
#include <cstdint>

// Problem constants
#define M_ROWS  200000      // BATCH * SIM_T
#define K_DIM   784
#define N1      100
#define T_STEPS 2000
#define BATCH   100
#define N2      10
// 3-phase split: t in [0,1000), [1000,1700), [1700,2000)
#define SP1     1000
#define SP2     1700
#define CH0     782         // ceil(100000/128)
#define CH1     547         // ceil(70000/128)
#define CH2     235         // ceil(30000/128)

// Scratch.
// g_z1 layout: [t][batch][c]  (row r' = t*100 + b). Padded to t=2008.
__device__ float  g_z1[(size_t)2008 * BATCH * N1];           // 80 MB
__device__ float  g_T1[(size_t)M_ROWS * N1];                 // 80 MB  [b][t][c]
__device__ float  g_z2t[(size_t)BATCH * N2 * T_STEPS + 16];  // 8 MB  [b*10+o][t]
__device__ int    g_flagA[800];                              // phase-1 chunk flags
__device__ int    g_flagB[560];                              // phase-2 chunk flags
__device__ int    g_flagC[256];                              // phase-3 chunk flags
__device__ float4 g_S1[BATCH * N1];                          // L1 state checkpoint
__device__ float4 g_S2[BATCH * N2];                          // L2 state checkpoint
__device__ __align__(16) __nv_bfloat16 g_W1h[112 * K_DIM];
__device__ __align__(16) __nv_bfloat16 g_W1l[112 * K_DIM];

// ---------------------------------------------------------------------------
// helpers
// ---------------------------------------------------------------------------
__device__ __forceinline__ unsigned pack_bf16x2(float fhi, float flo) {
    unsigned r;
    asm("cvt.rn.bf16x2.f32 %0, %1, %2;" : "=r"(r) : "f"(fhi), "f"(flo));
    return r;
}
__device__ __forceinline__ void mma_bf16(float* c, const unsigned* a,
                                         unsigned b0, unsigned b1) {
    asm("mma.sync.aligned.m16n8k16.row.col.f32.bf16.bf16.f32 "
        "{%0,%1,%2,%3}, {%4,%5,%6,%7}, {%8,%9}, {%0,%1,%2,%3};"
        : "+f"(c[0]), "+f"(c[1]), "+f"(c[2]), "+f"(c[3])
        : "r"(a[0]), "r"(a[1]), "r"(a[2]), "r"(a[3]), "r"(b0), "r"(b1));
}

// ---------------------------------------------------------------------------
// K0: convert W1 -> bf16 hi/lo (112 rows) + reset flags
// ---------------------------------------------------------------------------
__global__ void w1_convert_kernel(const float* __restrict__ W1) {
    int idx = blockIdx.x * 256 + threadIdx.x;
    if (idx < 800) g_flagA[idx] = 0;
    if (idx < 560) g_flagB[idx] = 0;
    if (idx < 256) g_flagC[idx] = 0;
    if (idx >= 112 * K_DIM) return;
    int r = idx / K_DIM;
    float w = (r < N1) ? W1[idx] : 0.f;
    __nv_bfloat16 hb = __float2bfloat16_rn(w);
    float hf = __bfloat162float(hb);
    g_W1h[idx] = hb;
    g_W1l[idx] = __float2bfloat16_rn(w - hf);
}

// ---------------------------------------------------------------------------
// HH step math (exact round-9 version)
// ---------------------------------------------------------------------------
__device__ __forceinline__ float ex2a(float x) {
    float r; asm("ex2.approx.f32 %0, %1;" : "=f"(r) : "f"(x)); return r;
}
__device__ __forceinline__ float rcpa(float x) {
    float r; asm("rcp.approx.f32 %0, %1;" : "=f"(r) : "f"(x)); return r;
}

#define L9   0.1602994489863f
#define L12  0.1202245867397f
#define L3   0.4808983469589f
#define BH_C 0.0023508962f
#define S0V  9.357622969e-14f

__device__ __forceinline__ float hh_step_t(float zk, float& V, float& m, float& n, float& h) {
    float mm   = m * m;
    float pow1 = 40.f * (mm * m) * h;
    float nn   = n * n;
    float pow2 = 35.f * (nn * nn);
    float Gs = 0.005f * (pow1 + pow2 + 0.3f);
    float E  = fmaf(pow1, 55.f, fmaf(pow2, -77.f, -19.5f));
    float num = fmaf(V, (1.f - Gs), 0.01f * (E + 1.5f + zk));
    float Vn = num * rcpa(1.f + Gs);

    float dM = Vn + 35.f;
    float dN = Vn - 25.f;
    float uM = ex2a(dM * L9);
    float uN = ex2a(dN * L9);
    float w  = ex2a((Vn + 90.f) * L12);
    float eS = ex2a((20.f - Vn) * L3);

    float um1M = uM - 1.f;
    float sM = 0.005f * dM * fmaf(0.182f, uM, 0.124f);
    float um1N = uN - 1.f;
    float sN = 0.005f * dN * fmaf(0.02f, uN, 0.002f);
    float sH = fmaf(0.005f * BH_C, w * w, 0.00125f);

    float rM = rcpa(um1M + sM);
    float rN = rcpa(um1N + sN);
    float rH = rcpa(w + sH);
    float rS = rcpa(1.f + eS);

    float mN = fmaf(0.00182f * dM, uM, (um1M - sM) * m) * rM;
    float nN = fmaf(0.0002f * dN, uN, (um1N - sN) * n) * rN;
    float hN = fmaf(w - sH, h, 0.0025f) * rH;

    if (Vn == 25.f)  nN = fmaf(0.99901f, n, 0.0018f) * (1.f / 1.00099f);
    if (Vn == -35.f) mN = fmaf(0.98623f, m, 0.01638f) * (1.f / 1.01377f);

    m = mN; n = nN; h = hN;
    V = Vn;
    return rS;
}

// ---------------------------------------------------------------------------
// wait until chunk flags [clo, chi] are all set (warp-parallel volatile poll)
// ---------------------------------------------------------------------------
__device__ __forceinline__ void wait_chunks(const int* flags, int clo, int chi) {
    const int lane = threadIdx.x & 31;
    for (int base = clo; base <= chi; base += 32) {
        int cid = min(base + lane, chi);
        while (__any_sync(0xffffffffu, ((volatile const int*)flags)[cid] == 0))
            __nanosleep(64);
    }
    __threadfence();
}

// ---------------------------------------------------------------------------
// K: fused GEMM-phase + L1-phase (+ L2-part in phases 1,2).
//   blocks [0,100): L1 producer, batch blk (R15 mechanism; state checkpointed
//                   at phase boundaries).
//   phases 1,2, blocks [100,108): L2 part (inputs fully ready at launch).
//   remaining blocks: GEMM chunk for this phase, publishes flag.
// ---------------------------------------------------------------------------
#define NSTAGE 49

__global__ void __launch_bounds__(256, 2)
fused_phase(const float* __restrict__ A, float* __restrict__ out, int phase) {
    __shared__ unsigned Ahs[2][128 * 8];
    __shared__ unsigned Als[2][128 * 8];
    __shared__ unsigned Bhs[2][112 * 8];
    __shared__ unsigned Bls[2][112 * 8];

    const int blk = blockIdx.x;
    const int tid = threadIdx.x;

    int s0, len, roff, maxc;
    int* flags;
    if (phase == 0)      { s0 = 0;    len = SP1;            roff = 0;          flags = g_flagA; maxc = CH0 - 1; }
    else if (phase == 1) { s0 = SP1;  len = SP2 - SP1;      roff = SP1 * 100;  flags = g_flagB; maxc = CH1 - 1; }
    else                 { s0 = SP2;  len = T_STEPS - SP2;  roff = SP2 * 100;  flags = g_flagC; maxc = CH2 - 1; }
    const int gemmBase = BATCH + (phase ? 8 : 0);

    if (blk < BATCH) {
        // ============ L1 producer, batch blk ============
        if (tid >= 128) return;
        const int b = blk;
        const bool act = (tid < N1);
        const int tcap = s0 + len - 1;

        float V = -70.f, m = 0.f, n = 0.f, h = 1.f;
        float p0 = 0.f, p1 = 0.f, p2 = 0.f, p3 = 0.f;

        const float* zq = g_z1 + (size_t)b * N1 + tid + (size_t)s0 * 10000;
        const float* zl = zq + 4 * 10000;
        float* ts = g_T1 + (size_t)b * T_STEPS * N1 + tid + (size_t)(s0 + 1) * N1;

        wait_chunks(flags, 0, 3);          // z1 t-rows s0..s0+3
        if (act) {
            if (phase == 0) {
                g_T1[(size_t)b * T_STEPS * N1 + tid] = S0V;   // T1 row 0
            } else {
                float4 st = g_S1[b * N1 + tid];
                V = st.x; m = st.y; n = st.z; h = st.w;
            }
            p0 = zq[0];
            p1 = zq[10000];
            p2 = zq[20000];
            p3 = zq[30000];
        }

#pragma unroll 1
        for (int w = 0; w < len / 50; w++) {
            const int wg = s0 / 50 + w;
            int tlo = wg * 50 + 4;
            int thi = min(wg * 50 + 53, tcap);
            int rlo = tlo * 100 - roff;
            int rhi = thi * 100 + 99 - roff;
            wait_chunks(flags, rlo >> 7, min(rhi >> 7, maxc));
            const int steps = (wg == 39) ? 49 : 50;
            if (act) {
#pragma unroll 2
                for (int j = 0; j < steps; j++) {
                    float zc = p0;
                    p0 = p1; p1 = p2; p2 = p3; p3 = *zl; zl += 10000;
                    *ts = hh_step_t(zc, V, m, n, h);
                    ts += N1;
                }
            }
        }
        if (act && phase < 2)
            g_S1[b * N1 + tid] = make_float4(V, m, n, h);
        return;
    }

    if (blk < gemmBase) {
        // ============ L2 part (phases 1,2; inputs fully ready) ============
        if (tid >= 128) return;
        const int idx = (blk - BATCH) * 128 + tid;
        if (idx >= BATCH * N2) return;
        const int b = idx / N2;
        const int o = idx - b * N2;

        const int t0     = (phase == 1) ? 0 : SP1;
        const int steps2 = (phase == 1) ? SP1 : (SP2 - SP1);   // 1000 / 700

        const float* zl = g_z2t + (size_t)idx * T_STEPS + t0;
        float* os = out + ((size_t)b * T_STEPS + t0) * N2 + o;

        float V = -70.f, m = 0.f, n = 0.f, h = 1.f;
        if (phase == 1) {
            *os = S0V;                 // out row 0
        } else {
            float4 st = g_S2[idx];
            V = st.x; m = st.y; n = st.z; h = st.w;
        }
        os += N2;                      // row t0+1

        float p0 = zl[0], p1 = zl[1], p2 = zl[2], p3 = zl[3];
        zl += 4;

#pragma unroll 1
        for (int s4 = 0; s4 < steps2; s4 += 4) {
#pragma unroll
            for (int j = 0; j < 4; j++) {
                float zc = p0;
                p0 = p1; p1 = p2; p2 = p3; p3 = *zl; zl++;
                *os = hh_step_t(zc, V, m, n, h);
                os += N2;
            }
        }
        g_S2[idx] = make_float4(V, m, n, h);
        return;
    }

    // ================= GEMM chunk (this phase) =================
    const int chunk = blk - gemmBase;
    const int row0  = roff + chunk * 128;
    const int limit = roff + len * 100;

    const int warp = tid >> 5, lane = tid & 31;
    const int g    = lane >> 2, tig = lane & 3;
    const int wm   = (warp >> 1) * 32;
    const int wn   = (warp & 1) * 56;

    // per-thread A row pointers (r' = t*100+b -> A row b*2000+t)
    const float* aptr[2];
    bool av[2];
    {
#pragma unroll
        for (int i = 0; i < 2; i++) {
            int idx = tid + i * 256;
            int rp = row0 + (idx >> 2);
            av[i] = rp < limit;
            int rc = av[i] ? rp : 0;
            int t = rc / 100;
            int bb = rc - t * 100;
            aptr[i] = A + (size_t)(bb * 2000 + t) * K_DIM + (idx & 3) * 4;
        }
    }

    float acc[2][7][4];
#pragma unroll
    for (int i = 0; i < 2; i++)
#pragma unroll
        for (int j = 0; j < 7; j++)
#pragma unroll
            for (int q = 0; q < 4; q++) acc[i][j][q] = 0.f;

    float4 va[2];
    unsigned vbh[4], vbl[4];

    auto ldg_stage = [&](int s) {
        int k0 = s * 16;
#pragma unroll
        for (int i = 0; i < 2; i++)
            va[i] = av[i] ? *(const float4*)(aptr[i] + k0)
                          : make_float4(0.f, 0.f, 0.f, 0.f);
#pragma unroll
        for (int i = 0; i < 4; i++) {
            int idx = tid + i * 256;
            if (idx < 896) {
                int r = idx >> 3, j = idx & 7;
                size_t off = (size_t)r * (K_DIM / 2) + (k0 >> 1) + j;
                vbh[i] = ((const unsigned*)g_W1h)[off];
                vbl[i] = ((const unsigned*)g_W1l)[off];
            }
        }
    };
    auto sts_stage = [&](int buf) {
#pragma unroll
        for (int i = 0; i < 2; i++) {
            int idx = tid + i * 256;
            int r = idx >> 2, q = idx & 3;
            float4 v = va[i];
            unsigned h0 = pack_bf16x2(v.y, v.x);
            unsigned h1 = pack_bf16x2(v.w, v.z);
            float f0h = __uint_as_float(h0 << 16);
            float f1h = __uint_as_float(h0 & 0xffff0000u);
            float f2h = __uint_as_float(h1 << 16);
            float f3h = __uint_as_float(h1 & 0xffff0000u);
            unsigned l0 = pack_bf16x2(v.y - f1h, v.x - f0h);
            unsigned l1 = pack_bf16x2(v.w - f3h, v.z - f2h);
            int sw = r & 7;
            Ahs[buf][r * 8 + ((2 * q)     ^ sw)] = h0;
            Ahs[buf][r * 8 + ((2 * q + 1) ^ sw)] = h1;
            Als[buf][r * 8 + ((2 * q)     ^ sw)] = l0;
            Als[buf][r * 8 + ((2 * q + 1) ^ sw)] = l1;
        }
#pragma unroll
        for (int i = 0; i < 4; i++) {
            int idx = tid + i * 256;
            if (idx < 896) {
                int r = idx >> 3, j = idx & 7;
                Bhs[buf][r * 8 + (j ^ (r & 7))] = vbh[i];
                Bls[buf][r * 8 + (j ^ (r & 7))] = vbl[i];
            }
        }
    };

    ldg_stage(0);
    sts_stage(0);
    __syncthreads();

#pragma unroll 1
    for (int s = 0; s < NSTAGE; s++) {
        if (s + 1 < NSTAGE) ldg_stage(s + 1);

        const int buf = s & 1;
        unsigned a_h[2][4], a_l[2][4];
#pragma unroll
        for (int mt = 0; mt < 2; mt++) {
            int r0 = wm + mt * 16 + g, r1 = r0 + 8;
            int sw0 = r0 & 7, sw1 = r1 & 7;
            a_h[mt][0] = Ahs[buf][r0 * 8 + (tig ^ sw0)];
            a_h[mt][1] = Ahs[buf][r1 * 8 + (tig ^ sw1)];
            a_h[mt][2] = Ahs[buf][r0 * 8 + ((tig + 4) ^ sw0)];
            a_h[mt][3] = Ahs[buf][r1 * 8 + ((tig + 4) ^ sw1)];
            a_l[mt][0] = Als[buf][r0 * 8 + (tig ^ sw0)];
            a_l[mt][1] = Als[buf][r1 * 8 + (tig ^ sw1)];
            a_l[mt][2] = Als[buf][r0 * 8 + ((tig + 4) ^ sw0)];
            a_l[mt][3] = Als[buf][r1 * 8 + ((tig + 4) ^ sw1)];
        }
#pragma unroll
        for (int nt = 0; nt < 7; nt++) {
            int n = wn + nt * 8 + g;
            int sn = n & 7;
            unsigned b0h = Bhs[buf][n * 8 + (tig ^ sn)];
            unsigned b1h = Bhs[buf][n * 8 + ((tig + 4) ^ sn)];
            unsigned b0l = Bls[buf][n * 8 + (tig ^ sn)];
            unsigned b1l = Bls[buf][n * 8 + ((tig + 4) ^ sn)];
#pragma unroll
            for (int mt = 0; mt < 2; mt++) {
                mma_bf16(acc[mt][nt], a_h[mt], b0h, b1h);
                mma_bf16(acc[mt][nt], a_h[mt], b0l, b1l);
                mma_bf16(acc[mt][nt], a_l[mt], b0h, b1h);
            }
        }

        if (s + 1 < NSTAGE) sts_stage((s + 1) & 1);
        __syncthreads();
    }

#pragma unroll
    for (int mt = 0; mt < 2; mt++) {
#pragma unroll
        for (int nt = 0; nt < 7; nt++) {
            int c = wn + nt * 8 + 2 * tig;
            if (c >= 99) continue;
            int r0g = row0 + wm + mt * 16 + g;
            if (r0g < limit) {
                float2 v = make_float2(acc[mt][nt][0], acc[mt][nt][1]);
                *(float2*)(g_z1 + (size_t)r0g * N1 + c) = v;
            }
            if (r0g + 8 < limit) {
                float2 v = make_float2(acc[mt][nt][2], acc[mt][nt][3]);
                *(float2*)(g_z1 + (size_t)(r0g + 8) * N1 + c) = v;
            }
        }
    }

    // publish chunk
    __threadfence();
    __syncthreads();
    if (tid == 0) atomicExch(&flags[chunk], 1);
}

// ---------------------------------------------------------------------------
// z2t[b*10+o][t] = sum_k T1[b][t][k] * W2[o][k]  for t in [toff, toff+cnt)
// ---------------------------------------------------------------------------
__global__ void __launch_bounds__(256, 4)
z2_part(const float* __restrict__ W2, int toff, int cnt) {
    __shared__ float W2s[N1][12];

    const int tid = threadIdx.x;
    for (int i = tid; i < N1 * 12; i += 256) {
        int k = i / 12, o = i - k * 12;
        W2s[k][o] = (o < N2) ? W2[o * N1 + k] : 0.f;
    }
    __syncthreads();

    const int u = blockIdx.x * 256 + tid;
    if (u >= BATCH * cnt) return;
    const int b = u / cnt;
    const int t = (u - b * cnt) + toff;

    const float4* tr = (const float4*)(g_T1 + ((size_t)b * T_STEPS + t) * N1);
    float acc[12];
#pragma unroll
    for (int o = 0; o < 12; o++) acc[o] = 0.f;

#pragma unroll 5
    for (int k4 = 0; k4 < 25; k4++) {
        float4 tv = tr[k4];
        const float* tf = &tv.x;
#pragma unroll
        for (int kk = 0; kk < 4; kk++) {
            int k = k4 * 4 + kk;
            float4 w0 = *(const float4*)&W2s[k][0];
            float4 w1 = *(const float4*)&W2s[k][4];
            float4 w2 = *(const float4*)&W2s[k][8];
            float f = tf[kk];
            acc[0] = fmaf(f, w0.x, acc[0]);  acc[1] = fmaf(f, w0.y, acc[1]);
            acc[2] = fmaf(f, w0.z, acc[2]);  acc[3] = fmaf(f, w0.w, acc[3]);
            acc[4] = fmaf(f, w1.x, acc[4]);  acc[5] = fmaf(f, w1.y, acc[5]);
            acc[6] = fmaf(f, w1.z, acc[6]);  acc[7] = fmaf(f, w1.w, acc[7]);
            acc[8] = fmaf(f, w2.x, acc[8]);  acc[9] = fmaf(f, w2.y, acc[9]);
        }
    }
#pragma unroll
    for (int o = 0; o < N2; o++)
        g_z2t[((size_t)b * N2 + o) * T_STEPS + t] = acc[o];
}

// ---------------------------------------------------------------------------
// L2 tail: steps 1700..1998 (state reloaded from checkpoint @ t=1700)
// ---------------------------------------------------------------------------
__global__ void __launch_bounds__(128, 1)
l2_tail(float* __restrict__ out) {
    const int idx = blockIdx.x * 128 + threadIdx.x;
    if (idx >= BATCH * N2) return;
    const int b = idx / N2;
    const int o = idx - b * N2;

    const float* zl = g_z2t + (size_t)idx * T_STEPS + SP2;
    float* os = out + ((size_t)b * T_STEPS + SP2 + 1) * N2 + o;

    float4 st = g_S2[idx];
    float V = st.x, m = st.y, n = st.z, h = st.w;

    float p0 = zl[0], p1 = zl[1], p2 = zl[2], p3 = zl[3];
    zl += 4;

    // 299 steps = 74*4 + 3
#pragma unroll 1
    for (int s4 = 0; s4 < 296; s4 += 4) {
#pragma unroll
        for (int j = 0; j < 4; j++) {
            float zc = p0;
            p0 = p1; p1 = p2; p2 = p3; p3 = *zl; zl++;
            *os = hh_step_t(zc, V, m, n, h);
            os += N2;
        }
    }
#pragma unroll
    for (int j = 0; j < 3; j++) {
        float zc = p0;
        p0 = p1; p1 = p2; p2 = p3; p3 = *zl; zl++;
        *os = hh_step_t(zc, V, m, n, h);
        os += N2;
    }
}

// ---------------------------------------------------------------------------
extern "C" void kernel_launch(void* const* d_in, const int* in_sizes, int n_in,
                              void* d_out, int out_size) {
    const float* batch = (const float*)d_in[0];   // (100, 2000, 784)
    const float* W1    = (const float*)d_in[1];   // (100, 784)
    const float* W2    = (const float*)d_in[2];   // (10, 100)
    float* out = (float*)d_out;                   // (100, 2000, 10)

    w1_convert_kernel<<<(112 * K_DIM + 255) / 256, 256>>>(W1);
    fused_phase<<<BATCH + CH0, 256>>>(batch, out, 0);          // GEMM p1 + L1 p1
    z2_part<<<(BATCH * SP1 + 255) / 256, 256>>>(W2, 0, SP1);
    fused_phase<<<BATCH + 8 + CH1, 256>>>(batch, out, 1);      // GEMM p2 + L1 p2 + L2 p1
    z2_part<<<(BATCH * (SP2 - SP1) + 255) / 256, 256>>>(W2, SP1, SP2 - SP1);
    fused_phase<<<BATCH + 8 + CH2, 256>>>(batch, out, 2);      // GEMM p3 + L1 p3 + L2 p2
    z2_part<<<(BATCH * (T_STEPS - SP2) + 255) / 256, 256>>>(W2, SP2, T_STEPS - SP2);
    l2_tail<<<8, 128>>>(out);                                  // L2 p3
}